// round 10
// baseline (speedup 1.0000x reference)
#include <cuda_runtime.h>
#include <cuda_bf16.h>
#include <mma.h>
#include <cstdint>

using namespace nvcuda;

#define NMAX    50000
#define NPAD    50048            // 391 * 128, full-tile stores stay in bounds
#define EMAX    800000
#define FEAT    128
#define HEADS   4
#define CH      32
#define NG      64
#define NCLS    10
#define NEG     0.2f
#define NLAYERS 3

// -------- static scratch; 16B-aligned --------
__device__ __align__(16) float g_xl  [NPAD * FEAT];   // xl' (NO bl bias)
__device__ __align__(16) float g_xr  [NPAD * FEAT];   // xr' (NO br bias)
__device__ __align__(16) float g_acc [NPAD * FEAT];
__device__ __align__(16) float g_pool[NG * FEAT];
__device__ __align__(16) float g_cnt [NG];
// CSR by destination
__device__ int g_cnti    [NMAX];
__device__ int g_cur     [NMAX];
__device__ int g_rowstart[NMAX + 1];
__device__ int g_col     [EMAX];
// bf16 weights, row-major [k][n]: per layer 4 tiles {Wl_hi, Wl_lo, Wr_hi, Wr_lo}
__device__ __align__(16) __nv_bfloat16 g_wbf[NLAYERS][4][FEAT * FEAT];

// -------- helpers --------
__device__ __forceinline__ void red_add4(float* addr, float a, float b, float c, float d) {
    asm volatile("red.global.add.v4.f32 [%0], {%1, %2, %3, %4};"
                 :: "l"(addr), "f"(a), "f"(b), "f"(c), "f"(d) : "memory");
}
__device__ __forceinline__ float elu_f(float v) { return v > 0.0f ? v : expm1f(v); }

__device__ __forceinline__ unsigned int pack_hi(float a, float b, float& ra, float& rb) {
    __nv_bfloat16 ha = __float2bfloat16(a), hb = __float2bfloat16(b);
    ra = a - __bfloat162float(ha);
    rb = b - __bfloat162float(hb);
    return ((unsigned)__bfloat16_as_ushort(hb) << 16) | (unsigned)__bfloat16_as_ushort(ha);
}
__device__ __forceinline__ unsigned int pack_lo(float a, float b) {
    __nv_bfloat16 ha = __float2bfloat16(a), hb = __float2bfloat16(b);
    return ((unsigned)__bfloat16_as_ushort(hb) << 16) | (unsigned)__bfloat16_as_ushort(ha);
}

// ================= init + CSR build (once per launch) =================
__global__ void init_all_k(int n) {
    int i = blockIdx.x * blockDim.x + threadIdx.x;
    if (i < n) { g_cnti[i] = 0; g_cur[i] = 0; }
    if (i < NG * FEAT) g_pool[i] = 0.0f;
    if (i < NG)        g_cnt[i]  = 0.0f;
}
__global__ void csr_hist_k(const int* __restrict__ dst, int E) {
    int e = blockIdx.x * blockDim.x + threadIdx.x;
    if (e < E) atomicAdd(&g_cnti[dst[e]], 1);
}
__global__ void csr_scan_k(int n) {
    __shared__ int part[1024];
    int t = threadIdx.x;
    int chunk = (n + 1023) / 1024;
    int b = t * chunk, e = min(b + chunk, n);
    int s = 0;
    for (int i = b; i < e; i++) s += g_cnti[i];
    part[t] = s;
    __syncthreads();
    #pragma unroll
    for (int off = 1; off < 1024; off <<= 1) {
        int v = (t >= off) ? part[t - off] : 0;
        __syncthreads();
        part[t] += v;
        __syncthreads();
    }
    int run = part[t] - s;
    for (int i = b; i < e; i++) { g_rowstart[i] = run; run += g_cnti[i]; }
    if (e == n && b < n) g_rowstart[n] = run;
}
__global__ void csr_scatter_k(const int* __restrict__ src, const int* __restrict__ dst, int E) {
    int e = blockIdx.x * blockDim.x + threadIdx.x;
    if (e >= E) return;
    int d = dst[e];
    int p = atomicAdd(&g_cur[d], 1);
    g_col[g_rowstart[d] + p] = src[e];
}

// ================= weight prep: fp32 W[k][n] -> bf16 hi/lo row-major =================
__global__ void prep_w_k(const float* __restrict__ Wl, const float* __restrict__ Wr) {
    int id = blockIdx.x * blockDim.x + threadIdx.x;
    if (id >= NLAYERS * 2 * FEAT * FEAT) return;
    int l   = id / (2 * FEAT * FEAT);
    int r   = id - l * 2 * FEAT * FEAT;
    int mat = r >> 14;
    int idx = r & 16383;
    const float* W = mat ? Wr : Wl;
    float w = W[l * FEAT * FEAT + idx];
    __nv_bfloat16 hi = __float2bfloat16(w);
    __nv_bfloat16 lo = __float2bfloat16(w - __bfloat162float(hi));
    g_wbf[l][mat * 2 + 0][idx] = hi;
    g_wbf[l][mat * 2 + 1][idx] = lo;
}

// ================= wmma bf16 GEMM: xl' = act@Wl, xr' = act@Wr (no bias) =================
// 256 threads, 128 rows/CTA, 8 warps x 16 rows. hi/lo split, fp32 accumulate.
// smem (bf16 elems, ld=136): A_hi[128x136], A_lo[128x136], W[4][128x136]
#define LDA 136
#define A_ELEMS (128 * LDA)                 // 17408
#define SMEM_BYTES (6 * A_ELEMS * 2)        // 208896

__global__ void __launch_bounds__(256, 1) gemm_wmma_k(const float* __restrict__ x_in,
                                                      int layer, int n) {
    extern __shared__ char sm8[];
    __nv_bfloat16* As_hi = (__nv_bfloat16*)sm8;
    __nv_bfloat16* As_lo = As_hi + A_ELEMS;
    __nv_bfloat16* Ws    = As_lo + A_ELEMS;   // 4 tiles of A_ELEMS
    int tid  = threadIdx.x;
    int base = blockIdx.x * 128;

    // A: convert fp32 -> bf16 hi/lo into smem (4 elems/thread/iter)
    for (int i = tid; i < 4096; i += 256) {
        int row = i >> 5, c4 = (i & 31) * 4;
        int node = base + row;
        float4 v = make_float4(0.f, 0.f, 0.f, 0.f);
        if (node < n) {
            if (layer == 0) {
                v = *(const float4*)&x_in[(size_t)node * FEAT + c4];
            } else {
                v = *(const float4*)&g_acc[(size_t)node * FEAT + c4];
                v.x = elu_f(v.x); v.y = elu_f(v.y); v.z = elu_f(v.z); v.w = elu_f(v.w);
            }
        }
        float rx, ry, rz, rw;
        uint2 hp, lp;
        hp.x = pack_hi(v.x, v.y, rx, ry);
        hp.y = pack_hi(v.z, v.w, rz, rw);
        lp.x = pack_lo(rx, ry);
        lp.y = pack_lo(rz, rw);
        *(uint2*)&As_hi[row * LDA + c4] = hp;
        *(uint2*)&As_lo[row * LDA + c4] = lp;
    }
    // W: copy 4 pre-converted tiles global->smem (restride 128 -> 136)
    {
        const uint4* wsrc = (const uint4*)&g_wbf[layer][0][0];
        for (int i = tid; i < 8192; i += 256) {
            int t = i >> 11, r = (i >> 4) & 127, c = i & 15;
            *(uint4*)((char*)Ws + (size_t)t * (A_ELEMS * 2) + r * (LDA * 2) + c * 16) = wsrc[i];
        }
    }
    __syncthreads();

    int wid = tid >> 5;
    int r0  = wid * 16;
    size_t node0 = (size_t)(base + r0);

    #pragma unroll
    for (int mat = 0; mat < 2; mat++) {
        wmma::fragment<wmma::accumulator, 16, 16, 16, float> c[8];
        #pragma unroll
        for (int nt = 0; nt < 8; nt++) wmma::fill_fragment(c[nt], 0.0f);

        const __nv_bfloat16* Wh = Ws + (mat * 2 + 0) * A_ELEMS;
        const __nv_bfloat16* Wl_ = Ws + (mat * 2 + 1) * A_ELEMS;

        #pragma unroll
        for (int k = 0; k < 8; k++) {
            wmma::fragment<wmma::matrix_a, 16, 16, 16, __nv_bfloat16, wmma::row_major> a_hi, a_lo;
            wmma::load_matrix_sync(a_hi, As_hi + r0 * LDA + k * 16, LDA);
            wmma::load_matrix_sync(a_lo, As_lo + r0 * LDA + k * 16, LDA);
            #pragma unroll
            for (int nt = 0; nt < 8; nt++) {
                wmma::fragment<wmma::matrix_b, 16, 16, 16, __nv_bfloat16, wmma::row_major> b_hi, b_lo;
                wmma::load_matrix_sync(b_hi, Wh  + (k * 16) * LDA + nt * 16, LDA);
                wmma::load_matrix_sync(b_lo, Wl_ + (k * 16) * LDA + nt * 16, LDA);
                wmma::mma_sync(c[nt], a_hi, b_hi, c[nt]);
                wmma::mma_sync(c[nt], a_hi, b_lo, c[nt]);
                wmma::mma_sync(c[nt], a_lo, b_hi, c[nt]);
            }
        }
        float* dstp = mat ? g_xr : g_xl;
        #pragma unroll
        for (int nt = 0; nt < 8; nt++)
            wmma::store_matrix_sync(dstp + node0 * FEAT + nt * 16, c[nt], FEAT, wmma::mem_row_major);
    }
}

// ================= fused edge pass: warp per destination node =================
// xl/xr are un-biased (xl', xr'). Score bias (bl+br) folds into xr4;
// output bias: out = sum(alpha*xl') + bl + bias  (since sum(alpha)=1).
#define SCORE4(x4, q)  do { \
    float _z; \
    _z = (x4).x + xr4.x; q = fmaf(fmaxf(_z, NEG * _z), a.x, q); \
    _z = (x4).y + xr4.y; q = fmaf(fmaxf(_z, NEG * _z), a.y, q); \
    _z = (x4).z + xr4.z; q = fmaf(fmaxf(_z, NEG * _z), a.z, q); \
    _z = (x4).w + xr4.w; q = fmaf(fmaxf(_z, NEG * _z), a.w, q); \
} while (0)

template <int POOL>
__global__ void dst_pass_k(const float* __restrict__ att,
                           const float* __restrict__ bl_p,
                           const float* __restrict__ br_p,
                           const float* __restrict__ bias,
                           const int* __restrict__ batch, int n) {
    int d    = (blockIdx.x * blockDim.x + threadIdx.x) >> 5;
    int lane = threadIdx.x & 31;
    if (d >= n) return;
    int c4 = lane * 4;

    float4 a   = *(const float4*)&att [c4];
    float4 bl4 = *(const float4*)&bl_p[c4];
    float4 br4 = *(const float4*)&br_p[c4];
    float4 bs4 = *(const float4*)&bias[c4];
    float4 xr4 = *(const float4*)&g_xr[(size_t)d * FEAT + c4];
    // fold score bias (bl+br) into xr4
    xr4.x += bl4.x + br4.x; xr4.y += bl4.y + br4.y;
    xr4.z += bl4.z + br4.z; xr4.w += bl4.w + br4.w;
    // output bias
    float4 ob4;
    ob4.x = bl4.x + bs4.x; ob4.y = bl4.y + bs4.y;
    ob4.z = bl4.z + bs4.z; ob4.w = bl4.w + bs4.w;

    float4 xld = *(const float4*)&g_xl[(size_t)d * FEAT + c4];

    float p = 0.0f;
    SCORE4(xld, p);
    p += __shfl_xor_sync(0xffffffffu, p, 1);
    p += __shfl_xor_sync(0xffffffffu, p, 2);
    p += __shfl_xor_sync(0xffffffffu, p, 4);
    float w = __expf(p);
    float4 acc0 = make_float4(w * xld.x, w * xld.y, w * xld.z, w * xld.w);
    float4 acc1 = make_float4(0.f, 0.f, 0.f, 0.f);
    float4 acc2 = make_float4(0.f, 0.f, 0.f, 0.f);
    float4 acc3 = make_float4(0.f, 0.f, 0.f, 0.f);
    float den0 = w, den1 = 0.f, den2 = 0.f, den3 = 0.f;

    int beg = g_rowstart[d], end = g_rowstart[d + 1];
    for (int j0 = beg; j0 < end; j0 += 32) {
        int sv = 0;
        if (j0 + lane < end) sv = g_col[j0 + lane];
        int cnt = min(32, end - j0);
        int k = 0;
        for (; k + 3 < cnt; k += 4) {
            int s0 = __shfl_sync(0xffffffffu, sv, k);
            int s1 = __shfl_sync(0xffffffffu, sv, k + 1);
            int s2 = __shfl_sync(0xffffffffu, sv, k + 2);
            int s3 = __shfl_sync(0xffffffffu, sv, k + 3);
            float4 x0 = *(const float4*)&g_xl[(size_t)s0 * FEAT + c4];
            float4 x1 = *(const float4*)&g_xl[(size_t)s1 * FEAT + c4];
            float4 x2 = *(const float4*)&g_xl[(size_t)s2 * FEAT + c4];
            float4 x3 = *(const float4*)&g_xl[(size_t)s3 * FEAT + c4];
            float q0 = 0.f, q1 = 0.f, q2 = 0.f, q3 = 0.f;
            SCORE4(x0, q0); SCORE4(x1, q1); SCORE4(x2, q2); SCORE4(x3, q3);
            q0 += __shfl_xor_sync(0xffffffffu, q0, 1);
            q1 += __shfl_xor_sync(0xffffffffu, q1, 1);
            q2 += __shfl_xor_sync(0xffffffffu, q2, 1);
            q3 += __shfl_xor_sync(0xffffffffu, q3, 1);
            q0 += __shfl_xor_sync(0xffffffffu, q0, 2);
            q1 += __shfl_xor_sync(0xffffffffu, q1, 2);
            q2 += __shfl_xor_sync(0xffffffffu, q2, 2);
            q3 += __shfl_xor_sync(0xffffffffu, q3, 2);
            q0 += __shfl_xor_sync(0xffffffffu, q0, 4);
            q1 += __shfl_xor_sync(0xffffffffu, q1, 4);
            q2 += __shfl_xor_sync(0xffffffffu, q2, 4);
            q3 += __shfl_xor_sync(0xffffffffu, q3, 4);
            float w0 = __expf(q0), w1 = __expf(q1), w2 = __expf(q2), w3 = __expf(q3);
            acc0.x = fmaf(w0, x0.x, acc0.x); acc1.x = fmaf(w1, x1.x, acc1.x);
            acc2.x = fmaf(w2, x2.x, acc2.x); acc3.x = fmaf(w3, x3.x, acc3.x);
            acc0.y = fmaf(w0, x0.y, acc0.y); acc1.y = fmaf(w1, x1.y, acc1.y);
            acc2.y = fmaf(w2, x2.y, acc2.y); acc3.y = fmaf(w3, x3.y, acc3.y);
            acc0.z = fmaf(w0, x0.z, acc0.z); acc1.z = fmaf(w1, x1.z, acc1.z);
            acc2.z = fmaf(w2, x2.z, acc2.z); acc3.z = fmaf(w3, x3.z, acc3.z);
            acc0.w = fmaf(w0, x0.w, acc0.w); acc1.w = fmaf(w1, x1.w, acc1.w);
            acc2.w = fmaf(w2, x2.w, acc2.w); acc3.w = fmaf(w3, x3.w, acc3.w);
            den0 += w0; den1 += w1; den2 += w2; den3 += w3;
        }
        for (; k < cnt; k++) {
            int s0 = __shfl_sync(0xffffffffu, sv, k);
            float4 x0 = *(const float4*)&g_xl[(size_t)s0 * FEAT + c4];
            float q0 = 0.f;
            SCORE4(x0, q0);
            q0 += __shfl_xor_sync(0xffffffffu, q0, 1);
            q0 += __shfl_xor_sync(0xffffffffu, q0, 2);
            q0 += __shfl_xor_sync(0xffffffffu, q0, 4);
            float w0 = __expf(q0);
            acc0.x = fmaf(w0, x0.x, acc0.x);
            acc0.y = fmaf(w0, x0.y, acc0.y);
            acc0.z = fmaf(w0, x0.z, acc0.z);
            acc0.w = fmaf(w0, x0.w, acc0.w);
            den0 += w0;
        }
    }

    float inv = 1.0f / ((den0 + den1) + (den2 + den3));
    float4 o;
    o.x = fmaf((acc0.x + acc1.x) + (acc2.x + acc3.x), inv, ob4.x);
    o.y = fmaf((acc0.y + acc1.y) + (acc2.y + acc3.y), inv, ob4.y);
    o.z = fmaf((acc0.z + acc1.z) + (acc2.z + acc3.z), inv, ob4.z);
    o.w = fmaf((acc0.w + acc1.w) + (acc2.w + acc3.w), inv, ob4.w);

    if (POOL) {
        o.x = elu_f(o.x); o.y = elu_f(o.y); o.z = elu_f(o.z); o.w = elu_f(o.w);
        int b = batch[d];
        red_add4(&g_pool[b * FEAT + c4], o.x, o.y, o.z, o.w);
        if (lane == 0) atomicAdd(&g_cnt[b], 1.0f);
    } else {
        *(float4*)&g_acc[(size_t)d * FEAT + c4] = o;
    }
}

// ================= classifier =================
__global__ void head_k(const float* __restrict__ lin_w, const float* __restrict__ lin_b,
                       float* __restrict__ out) {
    int g = blockIdx.x;
    int k = threadIdx.x;
    __shared__ float lg[NCLS];
    float inv = 1.0f / fmaxf(g_cnt[g], 1.0f);
    if (k < NCLS) {
        float acc = lin_b[k];
        for (int c = 0; c < FEAT; c++)
            acc = fmaf(g_pool[g * FEAT + c] * inv, lin_w[c * NCLS + k], acc);
        lg[k] = elu_f(acc);
    }
    __syncthreads();
    if (k < NCLS) {
        float m = lg[0];
        #pragma unroll
        for (int j = 1; j < NCLS; j++) m = fmaxf(m, lg[j]);
        float ssum = 0.0f;
        #pragma unroll
        for (int j = 0; j < NCLS; j++) ssum += expf(lg[j] - m);
        out[g * NCLS + k] = lg[k] - m - logf(ssum);
    }
}

// ================= launch =================
extern "C" void kernel_launch(void* const* d_in, const int* in_sizes, int n_in,
                              void* d_out, int out_size) {
    const float* x     = (const float*)d_in[0];
    const int*   ei    = (const int*)d_in[1];
    const int*   batch = (const int*)d_in[2];
    const float* Wl    = (const float*)d_in[3];
    const float* Wr    = (const float*)d_in[4];
    const float* bl    = (const float*)d_in[5];
    const float* br    = (const float*)d_in[6];
    const float* att   = (const float*)d_in[7];
    const float* bias  = (const float*)d_in[8];
    const float* lin_w = (const float*)d_in[9];
    const float* lin_b = (const float*)d_in[10];
    float*       out   = (float*)d_out;

    int E = in_sizes[1] / 2;
    int n = in_sizes[0] / FEAT;

    const int* src = ei;
    const int* dst = ei + E;

    static int smem_set = 0;
    if (!smem_set) {
        cudaFuncSetAttribute(gemm_wmma_k, cudaFuncAttributeMaxDynamicSharedMemorySize, SMEM_BYTES);
        smem_set = 1;
    }

    const int T = 256;
    int g_n    = (n + T - 1) / T;
    int g_e    = (E + T - 1) / T;
    int g_mma  = (n + 127) / 128;
    int g_dstW = (int)(((long long)n * 32 + T - 1) / T);
    int g_prep = (NLAYERS * 2 * FEAT * FEAT + T - 1) / T;

    init_all_k<<<g_n, T>>>(n);
    prep_w_k<<<g_prep, T>>>(Wl, Wr);
    csr_hist_k<<<g_e, T>>>(dst, E);
    csr_scan_k<<<1, 1024>>>(n);
    csr_scatter_k<<<g_e, T>>>(src, dst, E);

    for (int l = 0; l < NLAYERS; l++) {
        gemm_wmma_k<<<g_mma, 256, SMEM_BYTES>>>(x, l, n);
        if (l < NLAYERS - 1)
            dst_pass_k<0><<<g_dstW, T>>>(att + l * HEADS * CH, bl + l * FEAT, br + l * FEAT,
                                         bias + l * FEAT, batch, n);
        else
            dst_pass_k<1><<<g_dstW, T>>>(att + l * HEADS * CH, bl + l * FEAT, br + l * FEAT,
                                         bias + l * FEAT, batch, n);
    }

    head_k<<<NG, 32>>>(lin_w, lin_b, out);
}

// round 11
// speedup vs baseline: 1.6635x; 1.6635x over previous
#include <cuda_runtime.h>

#define NMAX    50000
#define EMAX    800000
#define FEAT    128
#define HEADS   4
#define CH      32
#define NG      64
#define NCLS    10
#define NEG     0.2f
#define NLAYERS 3

// -------- static scratch; 16B-aligned --------
__device__ __align__(16) float g_xl  [NMAX * FEAT];
__device__ __align__(16) float g_xr  [NMAX * FEAT];
__device__ __align__(16) float g_acc [NMAX * FEAT];
__device__ __align__(16) float g_pool[NG * FEAT];
__device__ __align__(16) float g_cnt [NG];
// CSR by destination
__device__ int g_cnti    [NMAX];
__device__ int g_cur     [NMAX];
__device__ int g_rowstart[NMAX + 1];
__device__ int g_col     [EMAX];
__device__ int g_bsum    [256];

// -------- helpers --------
__device__ __forceinline__ void red_add4(float* addr, float a, float b, float c, float d) {
    asm volatile("red.global.add.v4.f32 [%0], {%1, %2, %3, %4};"
                 :: "l"(addr), "f"(a), "f"(b), "f"(c), "f"(d) : "memory");
}
__device__ __forceinline__ float elu_f(float v) { return v > 0.0f ? v : expm1f(v); }

typedef unsigned long long u64;
__device__ __forceinline__ u64 pack2(float x, float y) {
    u64 r; asm("mov.b64 %0, {%1, %2};" : "=l"(r) : "f"(x), "f"(y)); return r;
}
__device__ __forceinline__ void unpack2(u64 v, float& x, float& y) {
    asm("mov.b64 {%0, %1}, %2;" : "=f"(x), "=f"(y) : "l"(v));
}
__device__ __forceinline__ void fma2(u64& d, u64 a, u64 b) {
    asm("fma.rn.f32x2 %0, %1, %2, %0;" : "+l"(d) : "l"(a), "l"(b));
}

// ================= init + CSR build (once per launch) =================
__global__ void init_all_k(int n) {
    int i = blockIdx.x * blockDim.x + threadIdx.x;
    if (i < n) { g_cnti[i] = 0; g_cur[i] = 0; }
    if (i < NG * FEAT) g_pool[i] = 0.0f;
    if (i < NG)        g_cnt[i]  = 0.0f;
}
__global__ void csr_hist_k(const int* __restrict__ dst, int E) {
    int e = blockIdx.x * blockDim.x + threadIdx.x;
    if (e < E) atomicAdd(&g_cnti[dst[e]], 1);
}

// ---- 3-phase parallel exclusive scan over g_cnti[0..n) -> g_rowstart ----
// phase 1: per-block (256 wide) exclusive scan; block totals to g_bsum
__global__ void csr_scan1_k(int n) {
    __shared__ int sh[256];
    int tid = threadIdx.x;
    int i = blockIdx.x * 256 + tid;
    int v = (i < n) ? g_cnti[i] : 0;
    sh[tid] = v;
    __syncthreads();
    #pragma unroll
    for (int off = 1; off < 256; off <<= 1) {
        int t = (tid >= off) ? sh[tid - off] : 0;
        __syncthreads();
        sh[tid] += t;
        __syncthreads();
    }
    if (i < n) g_rowstart[i] = sh[tid] - v;   // exclusive within block
    if (tid == 255) g_bsum[blockIdx.x] = sh[255];
}
// phase 2: one block scans the (<=256) block totals; writes grand total to rowstart[n]
__global__ void csr_scan2_k(int nb, int n) {
    __shared__ int sh[256];
    int tid = threadIdx.x;
    int v = (tid < nb) ? g_bsum[tid] : 0;
    sh[tid] = v;
    __syncthreads();
    #pragma unroll
    for (int off = 1; off < 256; off <<= 1) {
        int t = (tid >= off) ? sh[tid - off] : 0;
        __syncthreads();
        sh[tid] += t;
        __syncthreads();
    }
    if (tid < nb) g_bsum[tid] = sh[tid] - v;  // exclusive block offsets
    if (tid == 255) g_rowstart[n] = sh[255];
}
// phase 3: add block offsets
__global__ void csr_scan3_k(int n) {
    int i = blockIdx.x * 256 + threadIdx.x;
    if (i < n) g_rowstart[i] += g_bsum[blockIdx.x];
}

__global__ void csr_scatter_k(const int* __restrict__ src, const int* __restrict__ dst, int E) {
    int e = blockIdx.x * blockDim.x + threadIdx.x;
    if (e >= E) return;
    int d = dst[e];
    int p = atomicAdd(&g_cur[d], 1);
    g_col[g_rowstart[d] + p] = src[e];
}

// ================= fused GEMM: xl = act@Wl+bl, xr = act@Wr+br =================
// 128 threads/block, 32 rows/block. Thread: cols c4..c4+3, rows rh*8..rh*8+7.
__global__ void gemm_lr_k(const float* __restrict__ x_in, int layer,
                          const float* __restrict__ Wl, const float* __restrict__ Wr,
                          const float* __restrict__ bl, const float* __restrict__ br,
                          int n) {
    __shared__ float xs[32][FEAT + 4];
    int tid  = threadIdx.x;
    int base = blockIdx.x * 32;

    #pragma unroll
    for (int j = 0; j < 8; j++) {
        int idx4 = tid + j * 128;
        int r = idx4 >> 5, c4l = (idx4 & 31) * 4;
        int node = base + r;
        float4 v = make_float4(0.f, 0.f, 0.f, 0.f);
        if (node < n) {
            if (layer == 0) {
                v = *(const float4*)&x_in[node * FEAT + c4l];
            } else {
                v = *(const float4*)&g_acc[node * FEAT + c4l];
                v.x = elu_f(v.x); v.y = elu_f(v.y); v.z = elu_f(v.z); v.w = elu_f(v.w);
            }
        }
        *(float4*)&xs[r][c4l] = v;
    }
    __syncthreads();

    int cp = tid & 31;
    int rh = tid >> 5;

    const ulonglong2* Wl4 = (const ulonglong2*)Wl;
    const ulonglong2* Wr4 = (const ulonglong2*)Wr;

    u64 aL0[8], aL1[8], aR0[8], aR1[8];
    #pragma unroll
    for (int i = 0; i < 8; i++) { aL0[i]=0ull; aL1[i]=0ull; aR0[i]=0ull; aR1[i]=0ull; }

    #pragma unroll 4
    for (int k = 0; k < FEAT; k++) {
        ulonglong2 wl = Wl4[k * 32 + cp];
        ulonglong2 wr = Wr4[k * 32 + cp];
        #pragma unroll
        for (int i = 0; i < 8; i++) {
            float xv = xs[rh * 8 + i][k];
            u64 xv2 = pack2(xv, xv);
            fma2(aL0[i], xv2, wl.x);
            fma2(aL1[i], xv2, wl.y);
            fma2(aR0[i], xv2, wr.x);
            fma2(aR1[i], xv2, wr.y);
        }
    }

    int c4 = cp * 4;
    float4 bL = *(const float4*)&bl[c4];
    float4 bR = *(const float4*)&br[c4];
    #pragma unroll
    for (int i = 0; i < 8; i++) {
        int node = base + rh * 8 + i;
        if (node < n) {
            float4 o;
            unpack2(aL0[i], o.x, o.y); unpack2(aL1[i], o.z, o.w);
            o.x += bL.x; o.y += bL.y; o.z += bL.z; o.w += bL.w;
            *(float4*)&g_xl[(size_t)node * FEAT + c4] = o;
            unpack2(aR0[i], o.x, o.y); unpack2(aR1[i], o.z, o.w);
            o.x += bR.x; o.y += bR.y; o.z += bR.z; o.w += bR.w;
            *(float4*)&g_xr[(size_t)node * FEAT + c4] = o;
        }
    }
}

// ================= fused edge pass: warp per destination node =================
#define SCORE4(x4, q)  do { \
    float _z; \
    _z = (x4).x + xr4.x; q = fmaf(fmaxf(_z, NEG * _z), a.x, q); \
    _z = (x4).y + xr4.y; q = fmaf(fmaxf(_z, NEG * _z), a.y, q); \
    _z = (x4).z + xr4.z; q = fmaf(fmaxf(_z, NEG * _z), a.z, q); \
    _z = (x4).w + xr4.w; q = fmaf(fmaxf(_z, NEG * _z), a.w, q); \
} while (0)

template <int POOL>
__global__ void dst_pass_k(const float* __restrict__ att,
                           const float* __restrict__ bias,
                           const int* __restrict__ batch, int n) {
    int d    = (blockIdx.x * blockDim.x + threadIdx.x) >> 5;
    int lane = threadIdx.x & 31;
    if (d >= n) return;
    int c4 = lane * 4;

    float4 a   = *(const float4*)&att [c4];
    float4 xr4 = *(const float4*)&g_xr[(size_t)d * FEAT + c4];
    float4 xld = *(const float4*)&g_xl[(size_t)d * FEAT + c4];

    float p = 0.0f;
    SCORE4(xld, p);
    p += __shfl_xor_sync(0xffffffffu, p, 1);
    p += __shfl_xor_sync(0xffffffffu, p, 2);
    p += __shfl_xor_sync(0xffffffffu, p, 4);
    float w = __expf(p);
    float4 acc0 = make_float4(w * xld.x, w * xld.y, w * xld.z, w * xld.w);
    float4 acc1 = make_float4(0.f, 0.f, 0.f, 0.f);
    float4 acc2 = make_float4(0.f, 0.f, 0.f, 0.f);
    float4 acc3 = make_float4(0.f, 0.f, 0.f, 0.f);
    float den0 = w, den1 = 0.f, den2 = 0.f, den3 = 0.f;

    int beg = g_rowstart[d], end = g_rowstart[d + 1];
    for (int j0 = beg; j0 < end; j0 += 32) {
        int sv = 0;
        if (j0 + lane < end) sv = g_col[j0 + lane];
        int cnt = min(32, end - j0);
        int k = 0;
        for (; k + 3 < cnt; k += 4) {
            int s0 = __shfl_sync(0xffffffffu, sv, k);
            int s1 = __shfl_sync(0xffffffffu, sv, k + 1);
            int s2 = __shfl_sync(0xffffffffu, sv, k + 2);
            int s3 = __shfl_sync(0xffffffffu, sv, k + 3);
            float4 x0 = *(const float4*)&g_xl[(size_t)s0 * FEAT + c4];
            float4 x1 = *(const float4*)&g_xl[(size_t)s1 * FEAT + c4];
            float4 x2 = *(const float4*)&g_xl[(size_t)s2 * FEAT + c4];
            float4 x3 = *(const float4*)&g_xl[(size_t)s3 * FEAT + c4];
            float q0 = 0.f, q1 = 0.f, q2 = 0.f, q3 = 0.f;
            SCORE4(x0, q0); SCORE4(x1, q1); SCORE4(x2, q2); SCORE4(x3, q3);
            q0 += __shfl_xor_sync(0xffffffffu, q0, 1);
            q1 += __shfl_xor_sync(0xffffffffu, q1, 1);
            q2 += __shfl_xor_sync(0xffffffffu, q2, 1);
            q3 += __shfl_xor_sync(0xffffffffu, q3, 1);
            q0 += __shfl_xor_sync(0xffffffffu, q0, 2);
            q1 += __shfl_xor_sync(0xffffffffu, q1, 2);
            q2 += __shfl_xor_sync(0xffffffffu, q2, 2);
            q3 += __shfl_xor_sync(0xffffffffu, q3, 2);
            q0 += __shfl_xor_sync(0xffffffffu, q0, 4);
            q1 += __shfl_xor_sync(0xffffffffu, q1, 4);
            q2 += __shfl_xor_sync(0xffffffffu, q2, 4);
            q3 += __shfl_xor_sync(0xffffffffu, q3, 4);
            float w0 = __expf(q0), w1 = __expf(q1), w2 = __expf(q2), w3 = __expf(q3);
            acc0.x = fmaf(w0, x0.x, acc0.x); acc1.x = fmaf(w1, x1.x, acc1.x);
            acc2.x = fmaf(w2, x2.x, acc2.x); acc3.x = fmaf(w3, x3.x, acc3.x);
            acc0.y = fmaf(w0, x0.y, acc0.y); acc1.y = fmaf(w1, x1.y, acc1.y);
            acc2.y = fmaf(w2, x2.y, acc2.y); acc3.y = fmaf(w3, x3.y, acc3.y);
            acc0.z = fmaf(w0, x0.z, acc0.z); acc1.z = fmaf(w1, x1.z, acc1.z);
            acc2.z = fmaf(w2, x2.z, acc2.z); acc3.z = fmaf(w3, x3.z, acc3.z);
            acc0.w = fmaf(w0, x0.w, acc0.w); acc1.w = fmaf(w1, x1.w, acc1.w);
            acc2.w = fmaf(w2, x2.w, acc2.w); acc3.w = fmaf(w3, x3.w, acc3.w);
            den0 += w0; den1 += w1; den2 += w2; den3 += w3;
        }
        for (; k < cnt; k++) {
            int s0 = __shfl_sync(0xffffffffu, sv, k);
            float4 x0 = *(const float4*)&g_xl[(size_t)s0 * FEAT + c4];
            float q0 = 0.f;
            SCORE4(x0, q0);
            q0 += __shfl_xor_sync(0xffffffffu, q0, 1);
            q0 += __shfl_xor_sync(0xffffffffu, q0, 2);
            q0 += __shfl_xor_sync(0xffffffffu, q0, 4);
            float w0 = __expf(q0);
            acc0.x = fmaf(w0, x0.x, acc0.x);
            acc0.y = fmaf(w0, x0.y, acc0.y);
            acc0.z = fmaf(w0, x0.z, acc0.z);
            acc0.w = fmaf(w0, x0.w, acc0.w);
            den0 += w0;
        }
    }

    float inv = 1.0f / ((den0 + den1) + (den2 + den3));
    float4 b4 = *(const float4*)&bias[c4];
    float4 o;
    o.x = fmaf((acc0.x + acc1.x) + (acc2.x + acc3.x), inv, b4.x);
    o.y = fmaf((acc0.y + acc1.y) + (acc2.y + acc3.y), inv, b4.y);
    o.z = fmaf((acc0.z + acc1.z) + (acc2.z + acc3.z), inv, b4.z);
    o.w = fmaf((acc0.w + acc1.w) + (acc2.w + acc3.w), inv, b4.w);

    if (POOL) {
        o.x = elu_f(o.x); o.y = elu_f(o.y); o.z = elu_f(o.z); o.w = elu_f(o.w);
        int b = batch[d];
        red_add4(&g_pool[b * FEAT + c4], o.x, o.y, o.z, o.w);
        if (lane == 0) atomicAdd(&g_cnt[b], 1.0f);
    } else {
        *(float4*)&g_acc[(size_t)d * FEAT + c4] = o;
    }
}

// ================= classifier =================
__global__ void head_k(const float* __restrict__ lin_w, const float* __restrict__ lin_b,
                       float* __restrict__ out) {
    int g = blockIdx.x;
    int k = threadIdx.x;
    __shared__ float lg[NCLS];
    float inv = 1.0f / fmaxf(g_cnt[g], 1.0f);
    if (k < NCLS) {
        float acc = lin_b[k];
        for (int c = 0; c < FEAT; c++)
            acc = fmaf(g_pool[g * FEAT + c] * inv, lin_w[c * NCLS + k], acc);
        lg[k] = elu_f(acc);
    }
    __syncthreads();
    if (k < NCLS) {
        float m = lg[0];
        #pragma unroll
        for (int j = 1; j < NCLS; j++) m = fmaxf(m, lg[j]);
        float ssum = 0.0f;
        #pragma unroll
        for (int j = 0; j < NCLS; j++) ssum += expf(lg[j] - m);
        out[g * NCLS + k] = lg[k] - m - logf(ssum);
    }
}

// ================= launch =================
extern "C" void kernel_launch(void* const* d_in, const int* in_sizes, int n_in,
                              void* d_out, int out_size) {
    const float* x     = (const float*)d_in[0];
    const int*   ei    = (const int*)d_in[1];
    const int*   batch = (const int*)d_in[2];
    const float* Wl    = (const float*)d_in[3];
    const float* Wr    = (const float*)d_in[4];
    const float* bl    = (const float*)d_in[5];
    const float* br    = (const float*)d_in[6];
    const float* att   = (const float*)d_in[7];
    const float* bias  = (const float*)d_in[8];
    const float* lin_w = (const float*)d_in[9];
    const float* lin_b = (const float*)d_in[10];
    float*       out   = (float*)d_out;

    int E = in_sizes[1] / 2;
    int n = in_sizes[0] / FEAT;

    const int* src = ei;
    const int* dst = ei + E;

    const int T = 256;
    int g_n    = (n + T - 1) / T;
    int g_e    = (E + T - 1) / T;
    int g_gemm = (n + 31) / 32;
    int g_dstW = (int)(((long long)n * 32 + T - 1) / T);
    int nb     = (n + 255) / 256;   // scan blocks (<=256 for n<=65536)

    init_all_k<<<g_n, T>>>(n);
    csr_hist_k<<<g_e, T>>>(dst, E);
    csr_scan1_k<<<nb, 256>>>(n);
    csr_scan2_k<<<1, 256>>>(nb, n);
    csr_scan3_k<<<nb, 256>>>(n);
    csr_scatter_k<<<g_e, T>>>(src, dst, E);

    for (int l = 0; l < NLAYERS; l++) {
        gemm_lr_k<<<g_gemm, 128>>>(x, l,
                                   Wl + l * FEAT * FEAT, Wr + l * FEAT * FEAT,
                                   bl + l * FEAT, br + l * FEAT, n);
        if (l < NLAYERS - 1)
            dst_pass_k<0><<<g_dstW, T>>>(att + l * HEADS * CH, bias + l * FEAT, batch, n);
        else
            dst_pass_k<1><<<g_dstW, T>>>(att + l * HEADS * CH, bias + l * FEAT, batch, n);
    }

    head_k<<<NG, 32>>>(lin_w, lin_b, out);
}